// round 4
// baseline (speedup 1.0000x reference)
#include <cuda_runtime.h>
#include <math.h>

#define BB 64
#define SS 1024
#define II 512
#define HH 1024
#define OO 256
#define BH (BB * HH)

// persistent-kernel grid: 32 col-groups x 4 batch-groups
#define GC 32
#define GB 4
#define NBLK (GC * GB)
#define COLS_PB 32          // columns per block
#define ROWS_PB 16          // batch rows per block
#define KF 16               // K-split factor (k-groups per block)
#define KI 64               // iterations per k-group (1024 / KF)

// padded smem strides (floats)
#define WS 36               // Wh row stride: 4-aligned, dk=1 -> bank shift 4
#define HS 17               // h row stride: dk=1 -> bank shift 17
#define RKG 584             // red k-group stride (16 rows * 36 + 8), 4-aligned
#define RROW 36

#define SMEM_WH_FLOATS (1024 * WS)            // 36864 floats = 147456 B
#define SMEM_H_FLOATS  (1024 * HS)            // 17408 floats =  69632 B
#define SMEM_TOTAL_B   ((SMEM_WH_FLOATS + SMEM_H_FLOATS) * 4)

__device__ unsigned int g_bar;

// ---------------------------------------------------------------------------
// init: zero the grid barrier counter (must happen every replay)
// ---------------------------------------------------------------------------
__global__ void init_kernel() { g_bar = 0u; }

// ---------------------------------------------------------------------------
// Kernel 1: x_proj.  out_all[s*B*H + b*H + j] = dot(x[b,s,:], Wx[j,:]) + bias[j]
// ---------------------------------------------------------------------------
__global__ __launch_bounds__(256) void xproj_kernel(
    const float* __restrict__ x, const float* __restrict__ Wx,
    const float* __restrict__ bias, float* __restrict__ out)
{
    __shared__ float As[16][68];  // [k][b]
    __shared__ float Bs[16][68];  // [k][j]

    const int s  = blockIdx.y;
    const int n0 = blockIdx.x * 64;
    const int t  = threadIdx.x;
    const int tx = t & 15;
    const int ty = t >> 4;
    const int lb = t >> 2;
    const int lk = (t & 3) << 2;

    float acc[4][4];
#pragma unroll
    for (int r = 0; r < 4; r++)
#pragma unroll
        for (int c = 0; c < 4; c++) acc[r][c] = 0.0f;

    const float* xrow = x  + ((size_t)lb * SS + s) * II;
    const float* wrow = Wx + (size_t)(n0 + lb) * II;

    for (int kc = 0; kc < II; kc += 16) {
        float4 va = *(const float4*)(xrow + kc + lk);
        float4 vb = *(const float4*)(wrow + kc + lk);
        __syncthreads();
        As[lk + 0][lb] = va.x; As[lk + 1][lb] = va.y;
        As[lk + 2][lb] = va.z; As[lk + 3][lb] = va.w;
        Bs[lk + 0][lb] = vb.x; Bs[lk + 1][lb] = vb.y;
        Bs[lk + 2][lb] = vb.z; Bs[lk + 3][lb] = vb.w;
        __syncthreads();
#pragma unroll
        for (int k = 0; k < 16; k++) {
            float4 a = *(const float4*)&As[k][ty << 2];
            float4 w = *(const float4*)&Bs[k][tx << 2];
            acc[0][0] += a.x * w.x; acc[0][1] += a.x * w.y;
            acc[0][2] += a.x * w.z; acc[0][3] += a.x * w.w;
            acc[1][0] += a.y * w.x; acc[1][1] += a.y * w.y;
            acc[1][2] += a.y * w.z; acc[1][3] += a.y * w.w;
            acc[2][0] += a.z * w.x; acc[2][1] += a.z * w.y;
            acc[2][2] += a.z * w.z; acc[2][3] += a.z * w.w;
            acc[3][0] += a.w * w.x; acc[3][1] += a.w * w.y;
            acc[3][2] += a.w * w.z; acc[3][3] += a.w * w.w;
        }
    }

    const int jbase = n0 + (tx << 2);
    float4 bv = *(const float4*)&bias[jbase];
#pragma unroll
    for (int r = 0; r < 4; r++) {
        const int b = (ty << 2) + r;
        float4 o;
        o.x = acc[r][0] + bv.x; o.y = acc[r][1] + bv.y;
        o.z = acc[r][2] + bv.z; o.w = acc[r][3] + bv.w;
        *(float4*)&out[(size_t)s * BH + (size_t)b * HH + jbase] = o;
    }
}

// ---------------------------------------------------------------------------
// Kernel 2: persistent recurrence.  128 co-resident blocks, grid barrier per
// step.  Block (cg0 = bid % 32, bg = bid / 32) owns cols [cg0*32, +32) and
// batch rows [bg*16, +16).  Wh slice lives in smem for the whole kernel.
//   xp[b][j] <- tanh( xp[b][j] + sum_k hprev[b][k] * Wh[j][k] )   in place
// Thread tile: 4 rows x 8 cols, K split 16 ways with stride-16 interleave
// (k = kg + 16*i) so warps mix adjacent k-groups -> conflict-free smem.
// ---------------------------------------------------------------------------
__global__ __launch_bounds__(256, 1) void rnn_persistent(
    const float* __restrict__ Wh, float* __restrict__ all)
{
    extern __shared__ float smem[];
    float* whs = smem;                       // [1024][WS]
    float* h_s = smem + SMEM_WH_FLOATS;      // [1024][HS]; reused as red[]

    const int t   = threadIdx.x;
    const int bid = blockIdx.x;
    const int j0  = (bid & (GC - 1)) * COLS_PB;
    const int rb0 = (bid >> 5) * ROWS_PB;

    const int cg = t & 3;           // col group: cols cg*8 .. +7
    const int r4 = (t >> 2) & 3;    // row group: rows r4*4 .. +3
    const int kg = t >> 4;          // k group 0..15, k = kg + 16*i

    // ---- load resident Wh slice, transposed to [k][col] with pad WS ----
    for (int idx = t; idx < COLS_PB * 256; idx += 256) {
        const int c  = idx >> 8;         // 0..31
        const int kq = idx & 255;        // float4 index along K
        float4 v = *(const float4*)(Wh + (size_t)(j0 + c) * HH + (kq << 2));
        const int kb = (kq << 2) * WS + c;
        whs[kb]          = v.x;
        whs[kb + WS]     = v.y;
        whs[kb + 2 * WS] = v.z;
        whs[kb + 3 * WS] = v.w;
    }
    // no cross-block dependency on whs; barrier below synchronizes the block

    for (int s = 0; s < SS; s++) {
        float* cur = all + (size_t)s * BH;

        if (s > 0) {
            const float* hprev = all + (size_t)(s - 1) * BH;

            // ---- fill h tile [16 rows][1024 k] -> h_s[k][row], pad HS ----
            __syncthreads();   // red/h_s from previous step fully consumed
            for (int idx = t; idx < ROWS_PB * 256; idx += 256) {
                const int r  = idx >> 8;
                const int kq = idx & 255;
                float4 v = *(const float4*)(hprev + (size_t)(rb0 + r) * HH + (kq << 2));
                const int hb = (kq << 2) * HS + r;
                h_s[hb]          = v.x;
                h_s[hb + HS]     = v.y;
                h_s[hb + 2 * HS] = v.z;
                h_s[hb + 3 * HS] = v.w;
            }
            __syncthreads();

            // ---- main loop: acc[4][8] over 64 interleaved k ----
            float acc[4][8];
#pragma unroll
            for (int r = 0; r < 4; r++)
#pragma unroll
                for (int c = 0; c < 8; c++) acc[r][c] = 0.0f;

            int hb = kg * HS + (r4 << 2);
            int wb = kg * WS + (cg << 3);
#pragma unroll 4
            for (int i = 0; i < KI; i++) {
                const float h0 = h_s[hb + 0];
                const float h1 = h_s[hb + 1];
                const float h2 = h_s[hb + 2];
                const float h3 = h_s[hb + 3];
                const float4 wa = *(const float4*)&whs[wb];
                const float4 wc = *(const float4*)&whs[wb + 4];
                acc[0][0] += h0 * wa.x; acc[0][1] += h0 * wa.y;
                acc[0][2] += h0 * wa.z; acc[0][3] += h0 * wa.w;
                acc[0][4] += h0 * wc.x; acc[0][5] += h0 * wc.y;
                acc[0][6] += h0 * wc.z; acc[0][7] += h0 * wc.w;
                acc[1][0] += h1 * wa.x; acc[1][1] += h1 * wa.y;
                acc[1][2] += h1 * wa.z; acc[1][3] += h1 * wa.w;
                acc[1][4] += h1 * wc.x; acc[1][5] += h1 * wc.y;
                acc[1][6] += h1 * wc.z; acc[1][7] += h1 * wc.w;
                acc[2][0] += h2 * wa.x; acc[2][1] += h2 * wa.y;
                acc[2][2] += h2 * wa.z; acc[2][3] += h2 * wa.w;
                acc[2][4] += h2 * wc.x; acc[2][5] += h2 * wc.y;
                acc[2][6] += h2 * wc.z; acc[2][7] += h2 * wc.w;
                acc[3][0] += h3 * wa.x; acc[3][1] += h3 * wa.y;
                acc[3][2] += h3 * wa.z; acc[3][3] += h3 * wa.w;
                acc[3][4] += h3 * wc.x; acc[3][5] += h3 * wc.y;
                acc[3][6] += h3 * wc.z; acc[3][7] += h3 * wc.w;
                hb += 16 * HS;
                wb += 16 * WS;
            }

            // ---- K-split reduction via smem (aliases h_s) ----
            __syncthreads();               // done reading h_s
            float* red = h_s;              // [KF][16 rows][RROW pad]
#pragma unroll
            for (int ri = 0; ri < 4; ri++) {
                const int row = (r4 << 2) + ri;
                float4 a, b;
                a.x = acc[ri][0]; a.y = acc[ri][1]; a.z = acc[ri][2]; a.w = acc[ri][3];
                b.x = acc[ri][4]; b.y = acc[ri][5]; b.z = acc[ri][6]; b.w = acc[ri][7];
                const int rb = kg * RKG + row * RROW + (cg << 3);
                *(float4*)&red[rb]     = a;
                *(float4*)&red[rb + 4] = b;
            }
            __syncthreads();

            // ---- epilogue: 2 outputs/thread, + xp, tanh, store ----
#pragma unroll
            for (int oi = 0; oi < 2; oi++) {
                const int o   = t + (oi << 8);
                const int row = o >> 5;
                const int col = o & 31;
                float sum = 0.0f;
#pragma unroll
                for (int kk = 0; kk < KF; kk++)
                    sum += red[kk * RKG + row * RROW + col];
                float* p = cur + (size_t)(rb0 + row) * HH + j0 + col;
                *p = tanhf(*p + sum);
            }
        } else {
            // h0 = 0: h1 = tanh(xp)
#pragma unroll
            for (int oi = 0; oi < 2; oi++) {
                const int o   = t + (oi << 8);
                const int row = o >> 5;
                const int col = o & 31;
                float* p = cur + (size_t)(rb0 + row) * HH + j0 + col;
                *p = tanhf(*p);
            }
        }

        // ---- grid-wide barrier ----
        __threadfence();
        __syncthreads();
        if (t == 0) {
            atomicAdd(&g_bar, 1u);
            const unsigned target = (unsigned)(s + 1) * (unsigned)NBLK;
            while (*((volatile unsigned*)&g_bar) < target) { }
        }
        __syncthreads();
    }
}

// ---------------------------------------------------------------------------
// Kernel 3: readout.  y[b][o] = dot(h_last[b,:], Wout[o,:]) + bout[o]
// ---------------------------------------------------------------------------
__global__ __launch_bounds__(256) void readout_kernel(
    const float* __restrict__ hlast, const float* __restrict__ Wout,
    const float* __restrict__ bout, float* __restrict__ y)
{
    __shared__ float hs[HH];
    const int b = blockIdx.x;
    for (int i = threadIdx.x; i < HH; i += 256)
        hs[i] = hlast[(size_t)b * HH + i];
    __syncthreads();

    const int warp = threadIdx.x >> 5;
    const int lane = threadIdx.x & 31;
    for (int o = warp; o < OO; o += 8) {
        const float* wr = Wout + (size_t)o * HH;
        float a = 0.0f;
#pragma unroll 4
        for (int k = lane; k < HH; k += 32) a += hs[k] * wr[k];
#pragma unroll
        for (int off = 16; off; off >>= 1)
            a += __shfl_down_sync(0xffffffffu, a, off);
        if (lane == 0) y[(size_t)b * OO + o] = a + bout[o];
    }
}

// ---------------------------------------------------------------------------
extern "C" void kernel_launch(void* const* d_in, const int* in_sizes, int n_in,
                              void* d_out, int out_size)
{
    const float* x    = (const float*)d_in[0];
    const float* Wx   = (const float*)d_in[1];
    const float* Wh   = (const float*)d_in[2];
    const float* bias = (const float*)d_in[3];
    const float* Wout = (const float*)d_in[4];
    const float* bout = (const float*)d_in[5];

    float* y   = (float*)d_out;               // [64, 256]
    float* all = (float*)d_out + BB * OO;     // [1024, 64, 1024]

    cudaFuncSetAttribute(rnn_persistent,
                         cudaFuncAttributeMaxDynamicSharedMemorySize,
                         SMEM_TOTAL_B);

    init_kernel<<<1, 1>>>();

    dim3 g1(HH / 64, SS);
    xproj_kernel<<<g1, 256>>>(x, Wx, bias, all);

    rnn_persistent<<<NBLK, 256, SMEM_TOTAL_B>>>(Wh, all);

    readout_kernel<<<BB, 256>>>(all + (size_t)(SS - 1) * BH, Wout, bout, y);
}